// round 6
// baseline (speedup 1.0000x reference)
#include <cuda_runtime.h>

#define WID 512
#define HEI 512
#define NPIX (WID*HEI)
#define RAD 10
#define KS 21
#define VR 4
#define HW (WID + 2*RAD)   // 532
#define TPB 256
#define NUNITS (WID * (HEI / VR))   // 65536 column segments

// ---------------- compile-time weights (double-precision constexpr exp) ----------------
constexpr double cexp(double x) {
    double y = x / 16.0, s = 1.0, t = 1.0;
    for (int i = 1; i < 40; i++) { t *= y / (double)i; s += t; }
    s = s * s; s = s * s; s = s * s; s = s * s;
    return s;
}
constexpr double wgd(int t) { double d = (double)(t - RAD); return cexp(-d * d / 12.5); }
constexpr double wdd(int t) { double d = (double)(t - RAD); return cexp(-d * d * 9.0 / 200.0); }
constexpr double sumw(int wh) { double s = 0; for (int i = 0; i < KS; i++) s += (wh ? wgd(i) : wdd(i)); return s; }
constexpr double pref(int wh, int n) { double s = 0; for (int i = 0; i < n; i++) s += (wh ? wgd(i) : wdd(i)); return s; }

constexpr float SD_F    = (float)sumw(0);
constexpr float SG_F    = (float)sumw(1);
constexpr float SDINV_F = (float)(1.0 / (sumw(0) * sumw(0)));

#define TAPLIST(F) F(0) F(1) F(2) F(3) F(4) F(5) F(6) F(7) F(8) F(9) F(10) \
                   F(11) F(12) F(13) F(14) F(15) F(16) F(17) F(18) F(19) F(20)
#define DWG(i) constexpr float WG_##i = (float)wgd(i);
#define DWD(i) constexpr float WD_##i = (float)wdd(i);
TAPLIST(DWG)
TAPLIST(DWD)

__device__ __forceinline__ float wG(int t) {
    switch (t) {
#define CWG(i) case i: return WG_##i;
        TAPLIST(CWG)
#undef CWG
    }
    return 0.f;
}
__device__ __forceinline__ float wD(int t) {
    switch (t) {
#define CWD(i) case i: return WD_##i;
        TAPLIST(CWD)
#undef CWD
    }
    return 0.f;
}

__constant__ float c_pD[11] = {
    (float)pref(0,0),(float)pref(0,1),(float)pref(0,2),(float)pref(0,3),(float)pref(0,4),
    (float)pref(0,5),(float)pref(0,6),(float)pref(0,7),(float)pref(0,8),(float)pref(0,9),
    (float)pref(0,10)
};
__constant__ float c_pG[11] = {
    (float)pref(1,0),(float)pref(1,1),(float)pref(1,2),(float)pref(1,3),(float)pref(1,4),
    (float)pref(1,5),(float)pref(1,6),(float)pref(1,7),(float)pref(1,8),(float)pref(1,9),
    (float)pref(1,10)
};

__device__ __forceinline__ float hsD(int x) {
    float s = SD_F;
    if (x < RAD) s -= c_pD[RAD - x];
    if (x > WID - 1 - RAD) s -= c_pD[x - (WID - 1 - RAD)];
    return s;
}
__device__ __forceinline__ float hsG(int x) {
    float s = SG_F;
    if (x < RAD) s -= c_pG[RAD - x];
    if (x > WID - 1 - RAD) s -= c_pG[x - (WID - 1 - RAD)];
    return s;
}

// ---------------- static device scratch ----------------
__device__ float  g_gray[NPIX];
__device__ float  g_meanI[NPIX];
__device__ float  g_invvar[NPIX];
__device__ float  g_bnorm[NPIX];
__device__ float  g_s1[NPIX], g_s2[NPIX];
__device__ float  g_a1[NPIX], g_b1[NPIX];
__device__ float4 g_Q[NPIX];
__device__ float4 g_t1[NPIX], g_t2[NPIX], g_t3[NPIX];
__device__ float4 g_a[NPIX], g_b[NPIX], g_sp[NPIX];

// ---------------- grid barrier state ----------------
__device__ unsigned g_count = 0;
__device__ unsigned g_gen   = 0;

// ---------------- helpers ----------------
__device__ __forceinline__ float4 zero4() { return make_float4(0.f, 0.f, 0.f, 0.f); }
__device__ __forceinline__ void fma4(float4& a, float w, const float4& v) {
    a.x = fmaf(w, v.x, a.x); a.y = fmaf(w, v.y, a.y);
    a.z = fmaf(w, v.z, a.z); a.w = fmaf(w, v.w, a.w);
}
__device__ __forceinline__ float4 softmax4(float4 z) {
    float m = fmaxf(fmaxf(z.x, z.y), fmaxf(z.z, z.w));
    float ex = __expf(z.x - m), ey = __expf(z.y - m);
    float ez = __expf(z.z - m), ew = __expf(z.w - m);
    float inv = 1.f / (ex + ey + ez + ew);
    return make_float4(ex * inv, ey * inv, ez * inv, ew * inv);
}

// Release/acquire grid barrier. All blocks must be co-resident.
// __threadfence (gpu scope) emits CCTL.IVALL on sm_103a -> handles stale L1.
__device__ __forceinline__ unsigned gridbar(unsigned gen, int nb) {
    unsigned next = gen + 1;
    __threadfence();                 // release: drain this thread's writes to L2
    __syncthreads();
    if (threadIdx.x == 0) {
        if (atomicAdd(&g_count, 1) == (unsigned)(nb - 1)) {
            g_count = 0;
            __threadfence();
            atomicExch(&g_gen, next);
        } else {
            volatile unsigned* ph = &g_gen;
            while (*ph != next) { __nanosleep(40); }
        }
    }
    __syncthreads();
    __threadfence();                 // acquire: invalidate L1 before reading peers' data
    return next;
}

// ---------------- the single persistent kernel ----------------
__global__ void __launch_bounds__(TPB, 2)
k_crf(const float* __restrict__ img, const float4* __restrict__ unary,
      float4* __restrict__ dout, int nb) {
    __shared__ float smem[HW * 8];   // 17 KB union buffer
    float4* s4a = (float4*)smem;             // [HW] float4
    float4* s4b = (float4*)(smem + HW * 4);  // [HW] float4
    float*  s1  = smem;                      // [HW]
    float*  s2  = smem + HW;                 // [HW]
    float*  sG  = smem + HW * 4;             // [HW] (aliases s4b; phases don't overlap)

    const int tid = threadIdx.x;
    const int gid = blockIdx.x * TPB + tid;
    const int T   = nb * TPB;

    unsigned gen;
    {
        __shared__ unsigned sg;
        if (tid == 0) sg = *(volatile unsigned*)&g_gen;
        __syncthreads();
        gen = sg;
    }

    // ---- P0: grayscale + Q0 = softmax(-unary) ----
    for (int i = gid; i < NPIX; i += T) {
        float r = img[3 * i], gg = img[3 * i + 1], b = img[3 * i + 2];
        g_gray[i] = 0.2989f * r + 0.5870f * gg + 0.1140f * b;
        float4 u = unary[i];
        g_Q[i] = softmax4(make_float4(-u.x, -u.y, -u.z, -u.w));
    }
    gen = gridbar(gen, nb);

    // ---- P1: H pass of gray, gray^2 -> s1, s2 ----
    for (int y = blockIdx.x; y < HEI; y += nb) {
        for (int s = tid; s < HW; s += TPB) {
            int x = s - RAD; float a = 0.f, b = 0.f;
            if ((unsigned)x < WID) { a = g_gray[y * WID + x]; b = a * a; }
            s1[s] = a; s2[s] = b;
        }
        __syncthreads();
        int x0 = tid * 2;
        float A0 = 0.f, A1v = 0.f, B0 = 0.f, B1v = 0.f;
#pragma unroll
        for (int j = 0; j < KS + 1; j++) {
            float v1 = s1[x0 + j], v2 = s2[x0 + j];
            if (j < KS)  { A0  = fmaf(wD(j),     v1, A0);  B0  = fmaf(wD(j),     v2, B0);  }
            if (j >= 1)  { A1v = fmaf(wD(j - 1), v1, A1v); B1v = fmaf(wD(j - 1), v2, B1v); }
        }
        int o = y * WID + x0;
        g_s1[o] = A0; g_s1[o + 1] = A1v;
        g_s2[o] = B0; g_s2[o + 1] = B1v;
        __syncthreads();
    }
    gen = gridbar(gen, nb);

    // ---- P2: V pass -> meanI / invvar / a1 / b1 ----
    for (int u = gid; u < NUNITS; u += T) {
        int x = u & (WID - 1), y0 = (u >> 9) * VR;
        float A1[VR], A2[VR];
#pragma unroll
        for (int r = 0; r < VR; r++) { A1[r] = 0.f; A2[r] = 0.f; }
#pragma unroll
        for (int j = 0; j < KS + VR - 1; j++) {
            int row = y0 + j - RAD;
            float v1 = 0.f, v2 = 0.f;
            if ((unsigned)row < HEI) { int p = row * WID + x; v1 = g_s1[p]; v2 = g_s2[p]; }
#pragma unroll
            for (int r = 0; r < VR; r++) {
                int t = j - r;
                if (t >= 0 && t < KS) {
                    A1[r] = fmaf(wD(t), v1, A1[r]);
                    A2[r] = fmaf(wD(t), v2, A2[r]);
                }
            }
        }
        float hdx = hsD(x);
#pragma unroll
        for (int r = 0; r < VR; r++) {
            int y = y0 + r, idx = y * WID + x;
            float g = g_gray[idx];
            float mI  = (A1[r] - g) * SDINV_F;
            float mII = (A2[r] - g * g) * SDINV_F;
            float mp1 = (hdx * hsD(y) - 1.f) * SDINV_F;
            float var = mII - mI * mI;
            float iv  = 1.f / (var + 1e-4f);
            float a1  = mI * (1.f - mp1) * iv;
            float b1  = mp1 - a1 * mI;
            g_meanI[idx] = mI; g_invvar[idx] = iv; g_a1[idx] = a1; g_b1[idx] = b1;
        }
    }
    gen = gridbar(gen, nb);

    // ---- P3: H pass of a1, b1 -> s1, s2 ----
    for (int y = blockIdx.x; y < HEI; y += nb) {
        for (int s = tid; s < HW; s += TPB) {
            int x = s - RAD; float a = 0.f, b = 0.f;
            if ((unsigned)x < WID) { a = g_a1[y * WID + x]; b = g_b1[y * WID + x]; }
            s1[s] = a; s2[s] = b;
        }
        __syncthreads();
        int x0 = tid * 2;
        float A0 = 0.f, A1v = 0.f, B0 = 0.f, B1v = 0.f;
#pragma unroll
        for (int j = 0; j < KS + 1; j++) {
            float v1 = s1[x0 + j], v2 = s2[x0 + j];
            if (j < KS)  { A0  = fmaf(wD(j),     v1, A0);  B0  = fmaf(wD(j),     v2, B0);  }
            if (j >= 1)  { A1v = fmaf(wD(j - 1), v1, A1v); B1v = fmaf(wD(j - 1), v2, B1v); }
        }
        int o = y * WID + x0;
        g_s1[o] = A0; g_s1[o + 1] = A1v;
        g_s2[o] = B0; g_s2[o + 1] = B1v;
        __syncthreads();
    }
    gen = gridbar(gen, nb);

    // ---- P4: V pass -> bilateral norm ----
    for (int u = gid; u < NUNITS; u += T) {
        int x = u & (WID - 1), y0 = (u >> 9) * VR;
        float A1[VR], A2[VR];
#pragma unroll
        for (int r = 0; r < VR; r++) { A1[r] = 0.f; A2[r] = 0.f; }
#pragma unroll
        for (int j = 0; j < KS + VR - 1; j++) {
            int row = y0 + j - RAD;
            float v1 = 0.f, v2 = 0.f;
            if ((unsigned)row < HEI) { int p = row * WID + x; v1 = g_s1[p]; v2 = g_s2[p]; }
#pragma unroll
            for (int r = 0; r < VR; r++) {
                int t = j - r;
                if (t >= 0 && t < KS) {
                    A1[r] = fmaf(wD(t), v1, A1[r]);
                    A2[r] = fmaf(wD(t), v2, A2[r]);
                }
            }
        }
#pragma unroll
        for (int r = 0; r < VR; r++) {
            int idx = (y0 + r) * WID + x;
            float g = g_gray[idx];
            float gfa = (A1[r] - g_a1[idx]) * SDINV_F;
            float gfb = (A2[r] - g_b1[idx]) * SDINV_F;
            g_bnorm[idx] = gfa * g + gfb;
        }
    }
    gen = gridbar(gen, nb);

    // ---- 5 mean-field iterations ----
    for (int it = 0; it < 5; it++) {
        // P5: H pass of Q, gray*Q -> t1(G), t2(D), t3(D,grayQ)
        for (int y = blockIdx.x; y < HEI; y += nb) {
            const float4* Qrow = g_Q + y * WID;
            const float*  Grow = g_gray + y * WID;
            for (int s = tid; s < HW; s += TPB) {
                int x = s - RAD;
                float4 q = zero4(); float g = 0.f;
                if ((unsigned)x < WID) { q = Qrow[x]; g = Grow[x]; }
                s4a[s] = q; sG[s] = g;
            }
            __syncthreads();
            int x0 = tid * 2;
            float4 AG[2], AD[2], AI[2];
#pragma unroll
            for (int r = 0; r < 2; r++) { AG[r] = zero4(); AD[r] = zero4(); AI[r] = zero4(); }
#pragma unroll
            for (int j = 0; j < KS + 1; j++) {
                float4 q = s4a[x0 + j];
                float  g = sG[x0 + j];
                float4 gq = make_float4(q.x * g, q.y * g, q.z * g, q.w * g);
                if (j < KS) {
                    fma4(AG[0], wG(j), q); fma4(AD[0], wD(j), q); fma4(AI[0], wD(j), gq);
                }
                if (j >= 1) {
                    fma4(AG[1], wG(j - 1), q); fma4(AD[1], wD(j - 1), q); fma4(AI[1], wD(j - 1), gq);
                }
            }
            int o = y * WID + x0;
            g_t1[o] = AG[0]; g_t1[o + 1] = AG[1];
            g_t2[o] = AD[0]; g_t2[o + 1] = AD[1];
            g_t3[o] = AI[0]; g_t3[o + 1] = AI[1];
            __syncthreads();
        }
        gen = gridbar(gen, nb);

        // P6: V pass + elementwise -> a, b, sp
        for (int u = gid; u < NUNITS; u += T) {
            int x = u & (WID - 1), y0 = (u >> 9) * VR;
            float4 AG[VR], AD[VR], AI[VR];
#pragma unroll
            for (int r = 0; r < VR; r++) { AG[r] = zero4(); AD[r] = zero4(); AI[r] = zero4(); }
#pragma unroll
            for (int j = 0; j < KS + VR - 1; j++) {
                int row = y0 + j - RAD;
                float4 v1 = zero4(), v2 = zero4(), v3 = zero4();
                if ((unsigned)row < HEI) {
                    int p = row * WID + x;
                    v1 = g_t1[p]; v2 = g_t2[p]; v3 = g_t3[p];
                }
#pragma unroll
                for (int r = 0; r < VR; r++) {
                    int t = j - r;
                    if (t >= 0 && t < KS) {
                        fma4(AG[r], wG(t), v1);
                        fma4(AD[r], wD(t), v2);
                        fma4(AI[r], wD(t), v3);
                    }
                }
            }
            float hgx = hsG(x);
#pragma unroll
            for (int r = 0; r < VR; r++) {
                int y = y0 + r, idx = y * WID + x;
                float4 q = g_Q[idx];
                float g = g_gray[idx], mI = g_meanI[idx], iv = g_invvar[idx];
                float spc = 3.f / (hgx * hsG(y) - 1.f);
                float4 sp = make_float4((AG[r].x - q.x) * spc, (AG[r].y - q.y) * spc,
                                        (AG[r].z - q.z) * spc, (AG[r].w - q.w) * spc);
                float4 mp  = make_float4((AD[r].x - q.x) * SDINV_F, (AD[r].y - q.y) * SDINV_F,
                                         (AD[r].z - q.z) * SDINV_F, (AD[r].w - q.w) * SDINV_F);
                float4 mIp = make_float4((AI[r].x - g * q.x) * SDINV_F, (AI[r].y - g * q.y) * SDINV_F,
                                         (AI[r].z - g * q.z) * SDINV_F, (AI[r].w - g * q.w) * SDINV_F);
                float4 a = make_float4((mIp.x - mI * mp.x) * iv, (mIp.y - mI * mp.y) * iv,
                                       (mIp.z - mI * mp.z) * iv, (mIp.w - mI * mp.w) * iv);
                float4 b = make_float4(mp.x - a.x * mI, mp.y - a.y * mI,
                                       mp.z - a.z * mI, mp.w - a.w * mI);
                g_a[idx] = a; g_b[idx] = b; g_sp[idx] = sp;
            }
        }
        gen = gridbar(gen, nb);

        // P7: H pass of a, b -> t1, t2
        for (int y = blockIdx.x; y < HEI; y += nb) {
            const float4* Arow = g_a + y * WID;
            const float4* Brow = g_b + y * WID;
            for (int s = tid; s < HW; s += TPB) {
                int x = s - RAD;
                float4 a = zero4(), b = zero4();
                if ((unsigned)x < WID) { a = Arow[x]; b = Brow[x]; }
                s4a[s] = a; s4b[s] = b;
            }
            __syncthreads();
            int x0 = tid * 2;
            float4 AA[2], AB[2];
#pragma unroll
            for (int r = 0; r < 2; r++) { AA[r] = zero4(); AB[r] = zero4(); }
#pragma unroll
            for (int j = 0; j < KS + 1; j++) {
                float4 va = s4a[x0 + j], vb = s4b[x0 + j];
                if (j < KS)  { fma4(AA[0], wD(j), va);     fma4(AB[0], wD(j), vb);     }
                if (j >= 1)  { fma4(AA[1], wD(j - 1), va); fma4(AB[1], wD(j - 1), vb); }
            }
            int o = y * WID + x0;
            g_t1[o] = AA[0]; g_t1[o + 1] = AA[1];
            g_t2[o] = AB[0]; g_t2[o + 1] = AB[1];
            __syncthreads();
        }
        gen = gridbar(gen, nb);

        // P8: V pass of t1,t2 + message + softmax -> Q (or d_out)
        for (int u = gid; u < NUNITS; u += T) {
            int x = u & (WID - 1), y0 = (u >> 9) * VR;
            float4 AA[VR], AB[VR];
#pragma unroll
            for (int r = 0; r < VR; r++) { AA[r] = zero4(); AB[r] = zero4(); }
#pragma unroll
            for (int j = 0; j < KS + VR - 1; j++) {
                int row = y0 + j - RAD;
                float4 v1 = zero4(), v2 = zero4();
                if ((unsigned)row < HEI) { int p = row * WID + x; v1 = g_t1[p]; v2 = g_t2[p]; }
#pragma unroll
                for (int r = 0; r < VR; r++) {
                    int t = j - r;
                    if (t >= 0 && t < KS) {
                        fma4(AA[r], wD(t), v1);
                        fma4(AB[r], wD(t), v2);
                    }
                }
            }
#pragma unroll
            for (int r = 0; r < VR; r++) {
                int idx = (y0 + r) * WID + x;
                float g = g_gray[idx];
                float ibn = 10.f / g_bnorm[idx];
                float4 av = g_a[idx], bv = g_b[idx], sp = g_sp[idx], uu = unary[idx];
                float4 z;
                z.x = sp.x + ((AA[r].x - av.x) * SDINV_F * g + (AB[r].x - bv.x) * SDINV_F) * ibn - uu.x;
                z.y = sp.y + ((AA[r].y - av.y) * SDINV_F * g + (AB[r].y - bv.y) * SDINV_F) * ibn - uu.y;
                z.z = sp.z + ((AA[r].z - av.z) * SDINV_F * g + (AB[r].z - bv.z) * SDINV_F) * ibn - uu.z;
                z.w = sp.w + ((AA[r].w - av.w) * SDINV_F * g + (AB[r].w - bv.w) * SDINV_F) * ibn - uu.w;
                float4 qn = softmax4(z);
                if (it == 4) dout[idx] = qn; else g_Q[idx] = qn;
            }
        }
        if (it < 4) gen = gridbar(gen, nb);
    }
}

// ---------------- launch ----------------
extern "C" void kernel_launch(void* const* d_in, const int* in_sizes, int n_in,
                              void* d_out, int out_size) {
    const float* unary = nullptr;
    const float* image = nullptr;
    for (int i = 0; i < n_in; i++) {
        if (in_sizes[i] == NPIX * 4) unary = (const float*)d_in[i];
        else if (in_sizes[i] == NPIX * 3) image = (const float*)d_in[i];
    }

    // Size the grid for guaranteed co-residency (persistent kernel + grid barrier).
    int sms = 0, occ = 0;
    cudaDeviceGetAttribute(&sms, cudaDevAttrMultiProcessorCount, 0);
    cudaOccupancyMaxActiveBlocksPerMultiprocessor(&occ, k_crf, TPB, 0);
    if (sms <= 0) sms = 148;
    if (occ <= 0) occ = 1;
    int nb = sms * occ;
    if (nb > 1024) nb = 1024;

    k_crf<<<nb, TPB>>>(image, (const float4*)unary, (float4*)d_out, nb);
}